// round 17
// baseline (speedup 1.0000x reference)
#include <cuda_runtime.h>
#include <cuda_bf16.h>
#include <cuda_fp16.h>
#include <stdint.h>

// Problem constants
#define T_SEQ 512
#define BATCH 64
#define DIM   1024
#define LAT   1024
#define NPACK 4096            // 4*LAT, gate-interleaved packed columns: p = 4*j + g
#define M1    32768           // T_SEQ*BATCH
#define NCTA  128             // persistent grid (<=148 SMs, 1 CTA/SM)

// ---------------------------------------------------------------------------
// Device scratch (static __device__ arrays; no allocations anywhere)
// ---------------------------------------------------------------------------
__device__ float          g_gx[134217728];          // [M1][NPACK] fp32 x-part gates (512 MB)
__device__ __half         g_Wx16[4194304];          // Wx packed [NPACK][DIM] fp16
__device__ __half         g_Whh[4194304];           // Wh packed [NPACK][LAT] fp16
__device__ __half         g_x16[33554432];          // x         [M1][DIM]    fp16
__device__ __half         g_hh[2][65536];           // h state double-buffered, fp16
__device__ float          g_c[65536];               // c state fp32
__device__ float          g_bias[4096];             // packed bias
__device__ unsigned       g_bar_count;              // central grid barrier (proven)
__device__ unsigned       g_bar_phase;

// ---------------------------------------------------------------------------
// mma.sync m16n8k16 fp16 helper (fp32 accumulate)
// ---------------------------------------------------------------------------
__device__ __forceinline__ void mma_f16(float c[4], const uint32_t a[4], const uint32_t b[2]) {
    asm volatile(
        "mma.sync.aligned.m16n8k16.row.col.f32.f16.f16.f32 "
        "{%0,%1,%2,%3}, {%4,%5,%6,%7}, {%8,%9}, {%0,%1,%2,%3};\n"
        : "+f"(c[0]), "+f"(c[1]), "+f"(c[2]), "+f"(c[3])
        : "r"(a[0]), "r"(a[1]), "r"(a[2]), "r"(a[3]), "r"(b[0]), "r"(b[1]));
}

// cp.async helpers (16B, L2-only path: .cg)
__device__ __forceinline__ void cp_async16(void* sptr, const void* gptr) {
    uint32_t s = (uint32_t)__cvta_generic_to_shared(sptr);
    asm volatile("cp.async.cg.shared.global [%0], [%1], 16;\n" :: "r"(s), "l"(gptr));
}
__device__ __forceinline__ void cp_commit() { asm volatile("cp.async.commit_group;\n"); }
__device__ __forceinline__ void cp_wait1()  { asm volatile("cp.async.wait_group 1;\n"); }
__device__ __forceinline__ void cp_wait0()  { asm volatile("cp.async.wait_group 0;\n"); }

// ---------------------------------------------------------------------------
// Prep: transpose + gate-interleave + fp16 quantization of the 4 gate weights.
// x-rows (k<DIM) -> g_Wx16; h-rows (k>=DIM) -> g_Whh.  p = 4*j + g.
// ---------------------------------------------------------------------------
__global__ void prep_weights(const float* __restrict__ Wf, const float* __restrict__ Wi,
                             const float* __restrict__ Wo, const float* __restrict__ Wg) {
    __shared__ float tile[32][33];
    const int g  = blockIdx.z;
    const float* W = (g == 0) ? Wf : (g == 1) ? Wi : (g == 2) ? Wo : Wg;
    const int k0 = blockIdx.x * 32;     // 0..2047 (k index in D+L)
    const int j0 = blockIdx.y * 32;     // 0..1023
    const int tx = threadIdx.x & 31;
    const int ty = threadIdx.x >> 5;    // 0..7

    for (int r = ty; r < 32; r += 8)
        tile[r][tx] = W[(size_t)(k0 + r) * LAT + (j0 + tx)];
    __syncthreads();

    const bool isx = (k0 < DIM);
    for (int lj = ty; lj < 32; lj += 8) {
        float v = tile[tx][lj];                                   // (k0+tx, j0+lj)
        int p = 4 * (j0 + lj) + g;
        if (isx) {
            g_Wx16[(size_t)p * 1024 + (size_t)(k0 + tx)] = __float2half_rn(v);
        } else {
            g_Whh[(size_t)p * 1024 + (size_t)(k0 + tx - DIM)] = __float2half_rn(v);
        }
    }
}

// Pack bias gate-interleaved; zero initial h (buffer 0) and c; reset barrier.
__global__ void pack_bias_zero(const float* __restrict__ bf, const float* __restrict__ bi,
                               const float* __restrict__ bo, const float* __restrict__ bg) {
    int i = blockIdx.x * blockDim.x + threadIdx.x;   // 65536 threads
    if (i == 0) { g_bar_count = 0; g_bar_phase = 0; }
    if (i < 4096) {
        int gs = i & 3, j = i >> 2;
        const float* b = (gs == 0) ? bf : (gs == 1) ? bi : (gs == 2) ? bo : bg;
        g_bias[i] = b[j];
    }
    if (i < 65536) {
        g_c[i]     = 0.0f;
        g_hh[0][i] = __float2half_rn(0.0f);
    }
}

// Quantize x to fp16.
__global__ void split_x(const float* __restrict__ x) {
    size_t stride = (size_t)gridDim.x * blockDim.x;
    for (size_t i = (size_t)blockIdx.x * blockDim.x + threadIdx.x; i < 33554432u; i += stride)
        g_x16[i] = __float2half_rn(x[i]);
}

// ---------------------------------------------------------------------------
// GEMM1: gates_x[M1, NPACK] = x16[M1, DIM] @ Wx16[DIM, NPACK]   (fp16 x fp16)
// CTA tile 128x128, BK=32, 256 thr / 8 warps (2m x 4n), warp tile 64x32.
// 2-stage cp.async pipeline (dynamic smem, 40 KB/CTA).
// ---------------------------------------------------------------------------
typedef __half GTile[128][40];            // 10240 B
#define GEMM_SMEM 40960                   // 4 tiles (2 arrays x 2 stages)

__global__ __launch_bounds__(256) void gemm_x() {
    extern __shared__ __align__(16) unsigned char gsm[];
    GTile* Ash = (GTile*)(gsm);               // [2]
    GTile* Bsh = (GTile*)(gsm + 20480);       // [2]

    const int bm = blockIdx.x >> 5;          // 0..255
    const int bn = blockIdx.x & 31;          // 0..31   (n fastest: B tiles stay L2-hot)
    const size_t gm0 = (size_t)bm * 128;
    const size_t gn0 = (size_t)bn * 128;

    const int lane = threadIdx.x & 31, wid = threadIdx.x >> 5;
    const int wm = wid >> 2, wn = wid & 3;
    const int gid = lane >> 2, tig = lane & 3;

    float C[4][4][4];
    #pragma unroll
    for (int a = 0; a < 4; ++a)
        #pragma unroll
        for (int b = 0; b < 4; ++b)
            #pragma unroll
            for (int c = 0; c < 4; ++c) C[a][b][c] = 0.0f;

    auto load_slab = [&](int st, int it) {
        const int k0 = it * 32;
        #pragma unroll
        for (int s = threadIdx.x; s < 512; s += 256) {
            int r = s >> 2, q = (s & 3) * 8;
            cp_async16(&Ash[st][r][q], g_x16  + (gm0 + r) * 1024 + k0 + q);
            cp_async16(&Bsh[st][r][q], g_Wx16 + (gn0 + r) * 1024 + k0 + q);
        }
        cp_commit();
    };

    load_slab(0, 0);

    for (int it = 0; it < 32; ++it) {
        const int b = it & 1;
        if (it < 31) { load_slab(b ^ 1, it + 1); cp_wait1(); }
        else         { cp_wait0(); }
        __syncthreads();

        #pragma unroll
        for (int kk = 0; kk < 32; kk += 16) {
            const int cb = kk + 2 * tig;
            uint32_t ah[4][4], bh[4][2];
            #pragma unroll
            for (int mt = 0; mt < 4; ++mt) {
                int row = wm * 64 + mt * 16 + gid;
                ah[mt][0] = *(const uint32_t*)&Ash[b][row    ][cb    ];
                ah[mt][1] = *(const uint32_t*)&Ash[b][row + 8][cb    ];
                ah[mt][2] = *(const uint32_t*)&Ash[b][row    ][cb + 8];
                ah[mt][3] = *(const uint32_t*)&Ash[b][row + 8][cb + 8];
            }
            #pragma unroll
            for (int nt = 0; nt < 4; ++nt) {
                int nr = wn * 32 + nt * 8 + gid;
                bh[nt][0] = *(const uint32_t*)&Bsh[b][nr][cb    ];
                bh[nt][1] = *(const uint32_t*)&Bsh[b][nr][cb + 8];
            }
            #pragma unroll
            for (int mt = 0; mt < 4; ++mt)
                #pragma unroll
                for (int nt = 0; nt < 4; ++nt)
                    mma_f16(C[mt][nt], ah[mt], bh[nt]);
        }
        __syncthreads();
    }

    #pragma unroll
    for (int mt = 0; mt < 4; ++mt)
        #pragma unroll
        for (int nt = 0; nt < 4; ++nt) {
            size_t row = gm0 + wm * 64 + mt * 16 + gid;
            size_t col = gn0 + wn * 32 + nt * 8 + 2 * tig;
            *(float2*)&g_gx[row * 4096 + col]       = make_float2(C[mt][nt][0], C[mt][nt][1]);
            *(float2*)&g_gx[(row + 8) * 4096 + col] = make_float2(C[mt][nt][2], C[mt][nt][3]);
        }
}

// ---------------------------------------------------------------------------
// Persistent recurrent kernel — UNCHANGED from R15 (proven 6,831 us config).
// fp16 h x fp16 W, single term; central grid barrier; smem ~101 KB.
// ---------------------------------------------------------------------------
struct SmemLayout {
    __half Wh[32][1032];     // 66,048 B  padded: conflict-free frags
    __half Ah[2][64][136];   // 34,816    K-chunk 128, double buffered
};
#define SMEM_BYTES sizeof(SmemLayout)   // 100,864 B

__device__ __forceinline__ void grid_bar(unsigned target) {
    __syncthreads();
    if (threadIdx.x == 0) {
        __threadfence();
        unsigned prev = atomicAdd(&g_bar_count, 1);
        if (prev == NCTA - 1) {
            g_bar_count = 0;
            __threadfence();
            atomicAdd(&g_bar_phase, 1);
        } else {
            unsigned p;
            do {
                asm volatile("ld.acquire.gpu.global.u32 %0, [%1];"
                             : "=r"(p) : "l"(&g_bar_phase));
            } while (p < target);
        }
    }
    __syncthreads();
}

__device__ __forceinline__ void lstm_update(int t, int r, int j,
                                            float pf, float pi, float po, float pg,
                                            int wb, float* __restrict__ out) {
    float f  = 1.0f / (1.0f + __expf(-pf));
    float ii = 1.0f / (1.0f + __expf(-pi));
    float o  = 1.0f / (1.0f + __expf(-po));
    float gg = tanhf(pg);
    int idx  = r * 1024 + j;
    float cn = f * g_c[idx] + ii * gg;
    g_c[idx] = cn;
    float h  = o * tanhf(cn);
    out[(size_t)t * 65536 + idx] = h;
    g_hh[wb][idx] = __float2half_rn(h);
}

__global__ __launch_bounds__(256, 1) void lstm_persist(float* __restrict__ out) {
    extern __shared__ __align__(16) unsigned char smem_raw[];
    SmemLayout& S = *reinterpret_cast<SmemLayout*>(smem_raw);

    const int tid  = threadIdx.x;
    const int lane = tid & 31, wid = tid >> 5;
    const int mt = wid & 3, nh = wid >> 2;       // warp tile: rows 16*mt, cols 16*nh
    const int g8  = lane >> 2, tig = lane & 3;
    const int P0  = blockIdx.x * 32;
    const int row = mt * 16 + g8;

    // One-time weight slice load: 32 rows x 1024 k fp16 (64 KB) into smem.
    for (int s = tid; s < 4096; s += 256) {
        int r = s >> 7, q = (s & 127) * 8;
        *(uint4*)&S.Wh[r][q] = *(const uint4*)(g_Whh + (size_t)(P0 + r) * 1024 + q);
    }
    __syncthreads();

    // Loop-invariant: packed columns + bias for this thread's epilogue.
    int pcol[2];  float vb[2][2];
    #pragma unroll
    for (int nb = 0; nb < 2; ++nb) {
        pcol[nb] = P0 + nh * 16 + nb * 8 + 2 * tig;
        vb[nb][0] = g_bias[pcol[nb]];
        vb[nb][1] = g_bias[pcol[nb] + 1];
    }

    for (int t = 0; t < T_SEQ; ++t) {
        const int rb = t & 1, wb = rb ^ 1;
        const __half* __restrict__ hh = g_hh[rb];
        const float* __restrict__ gx = g_gx + (size_t)t * BATCH * 4096;

        // Prefetch this thread's gates_x operands (streaming; hidden by compute).
        float2 vg[2][2];
        #pragma unroll
        for (int nb = 0; nb < 2; ++nb) {
            int p = pcol[nb];
            vg[nb][0] = __ldcs((const float2*)&gx[(size_t)row * 4096 + p]);
            vg[nb][1] = __ldcs((const float2*)&gx[(size_t)(row + 8) * 4096 + p]);
        }

        float C[2][4] = {};

        // Preload chunk 0 of h (fp16 -> 1024 cp.async thread-slots).
        for (int s = tid; s < 1024; s += 256) {
            int r = s >> 4, q = (s & 15) * 8;
            cp_async16(&S.Ah[0][r][q], hh + r * 1024 + q);
        }
        cp_commit();

        for (int it = 0; it < 8; ++it) {
            if (it < 7) {
                const int k0 = (it + 1) * 128, b = (it + 1) & 1;
                for (int s = tid; s < 1024; s += 256) {
                    int r = s >> 4, q = (s & 15) * 8;
                    cp_async16(&S.Ah[b][r][q], hh + r * 1024 + k0 + q);
                }
                cp_commit();
                cp_wait1();
            } else {
                cp_wait0();
            }
            __syncthreads();
            const int b = it & 1;
            #pragma unroll
            for (int kk = 0; kk < 128; kk += 16) {
                const int ca = kk + 2 * tig;          // k within chunk (A)
                const int cw = it * 128 + ca;         // global k (W, fully resident)
                uint32_t ah[4];
                ah[0] = *(const uint32_t*)&S.Ah[b][row    ][ca    ];
                ah[1] = *(const uint32_t*)&S.Ah[b][row + 8][ca    ];
                ah[2] = *(const uint32_t*)&S.Ah[b][row    ][ca + 8];
                ah[3] = *(const uint32_t*)&S.Ah[b][row + 8][ca + 8];
                #pragma unroll
                for (int nb = 0; nb < 2; ++nb) {
                    const int nr = nh * 16 + nb * 8 + g8;
                    uint32_t bh[2];
                    bh[0] = *(const uint32_t*)&S.Wh[nr][cw    ];
                    bh[1] = *(const uint32_t*)&S.Wh[nr][cw + 8];
                    mma_f16(C[nb], ah, bh);
                }
            }
            __syncthreads();
        }

        // Epilogue: add x-part + bias, pair-exchange (f,i)<->(o,g), update cell.
        #pragma unroll
        for (int nb = 0; nb < 2; ++nb) {
            float v0 = C[nb][0] + vg[nb][0].x + vb[nb][0];
            float v1 = C[nb][1] + vg[nb][0].y + vb[nb][1];
            float v2 = C[nb][2] + vg[nb][1].x + vb[nb][0];
            float v3 = C[nb][3] + vg[nb][1].y + vb[nb][1];
            float q0 = __shfl_xor_sync(0xffffffffu, v0, 1);
            float q1 = __shfl_xor_sync(0xffffffffu, v1, 1);
            float q2 = __shfl_xor_sync(0xffffffffu, v2, 1);
            float q3 = __shfl_xor_sync(0xffffffffu, v3, 1);
            if ((lane & 1) == 0) {               // holds (f,i); partner held (o,g)
                int j = pcol[nb] >> 2;
                lstm_update(t, row,     j, v0, v1, q0, q1, wb, out);
                lstm_update(t, row + 8, j, v2, v3, q2, q3, wb, out);
            }
        }

        if (t < T_SEQ - 1) grid_bar((unsigned)(t + 1));
    }
}

// ---------------------------------------------------------------------------
// Launch: default stream, fully capturable; one persistent recurrent kernel.
// ---------------------------------------------------------------------------
extern "C" void kernel_launch(void* const* d_in, const int* in_sizes, int n_in,
                              void* d_out, int out_size) {
    const float* x  = (const float*)d_in[0];
    const float* Wf = (const float*)d_in[1];
    const float* bf = (const float*)d_in[2];
    const float* Wi = (const float*)d_in[3];
    const float* bi = (const float*)d_in[4];
    const float* Wo = (const float*)d_in[5];
    const float* bo = (const float*)d_in[6];
    const float* Wg = (const float*)d_in[7];
    const float* bg = (const float*)d_in[8];
    float* out = (float*)d_out;

    cudaFuncSetAttribute(gemm_x, cudaFuncAttributeMaxDynamicSharedMemorySize,
                         GEMM_SMEM);
    cudaFuncSetAttribute(lstm_persist, cudaFuncAttributeMaxDynamicSharedMemorySize,
                         (int)SMEM_BYTES);

    prep_weights<<<dim3(64, 32, 4), 256>>>(Wf, Wi, Wo, Wg);
    pack_bias_zero<<<256, 256>>>(bf, bi, bo, bg);
    split_x<<<8192, 256>>>(x);
    gemm_x<<<8192, 256, GEMM_SMEM>>>();
    lstm_persist<<<NCTA, 256, SMEM_BYTES>>>(out);
}